// round 5
// baseline (speedup 1.0000x reference)
#include <cuda_runtime.h>
#include <cstdint>

#define NN 100000
#define NE 1600000
#define DF 64
#define NB 98   // ceil(NN / 1024)

// Scratch (allocation-free rule: __device__ globals)
__device__ int g_cnt[NN];        // degree counts, then bucket cursors
__device__ int g_off[NN + 1];    // CSR offsets
__device__ int g_bsum[128];      // per-block sums for the scan
__device__ int g_eidx[NE];       // CSR: src index per slot, grouped by dst

// ---------------------------------------------------------------------------
// K0: zero degree counters (graph replays require re-zeroing)
// ---------------------------------------------------------------------------
__global__ void zero_kernel() {
    int tid = blockIdx.x * blockDim.x + threadIdx.x;
    if (tid < NN) g_cnt[tid] = 0;
}

// ---------------------------------------------------------------------------
// K1: count in-degree per dst. 4 edges/thread (int4 load) for MLP.
// ---------------------------------------------------------------------------
__global__ void count_kernel(const int* __restrict__ dst, int E) {
    int i = (blockIdx.x * blockDim.x + threadIdx.x) * 4;
    if (i + 3 < E) {
        int4 d = *reinterpret_cast<const int4*>(dst + i);
        atomicAdd(&g_cnt[d.x], 1);
        atomicAdd(&g_cnt[d.y], 1);
        atomicAdd(&g_cnt[d.z], 1);
        atomicAdd(&g_cnt[d.w], 1);
    } else {
        for (int u = 0; u < 4 && i + u < E; u++)
            atomicAdd(&g_cnt[dst[i + u]], 1);
    }
}

// ---------------------------------------------------------------------------
// K2a: per-block (1024 elems) local exclusive scan of g_cnt -> g_off,
//      block totals -> g_bsum.
// ---------------------------------------------------------------------------
__global__ void __launch_bounds__(1024)
scanA_kernel() {
    __shared__ int wsum[32];
    const int tid = threadIdx.x;
    const int lane = tid & 31;
    const int wid = tid >> 5;
    int gid = blockIdx.x * 1024 + tid;

    int v = (gid < NN) ? g_cnt[gid] : 0;
    int x = v;
#pragma unroll
    for (int o = 1; o < 32; o <<= 1) {
        int t = __shfl_up_sync(0xffffffffu, x, o);
        if (lane >= o) x += t;
    }
    if (lane == 31) wsum[wid] = x;
    __syncthreads();
    if (tid < 32) {
        int y = wsum[tid];
#pragma unroll
        for (int o = 1; o < 32; o <<= 1) {
            int t = __shfl_up_sync(0xffffffffu, y, o);
            if (tid >= o) y += t;
        }
        wsum[tid] = y;
    }
    __syncthreads();
    int base = (wid > 0) ? wsum[wid - 1] : 0;
    int incl = x + base;
    if (gid < NN) g_off[gid] = incl - v;           // local exclusive
    if (tid == 1023) g_bsum[blockIdx.x] = incl;    // block total
}

// ---------------------------------------------------------------------------
// K2b: add block base (computed inline by warp-reducing prior block sums);
//      init bucket cursors. Folds the old scanB launch away.
// ---------------------------------------------------------------------------
__global__ void __launch_bounds__(1024)
scanC_kernel(int E) {
    __shared__ int sbase;
    const int bid = blockIdx.x;
    if (threadIdx.x < 32) {
        int base = 0;
        for (int i = threadIdx.x; i < bid; i += 32) base += g_bsum[i];
#pragma unroll
        for (int o = 16; o > 0; o >>= 1)
            base += __shfl_down_sync(0xffffffffu, base, o);
        if (threadIdx.x == 0) sbase = base;
    }
    __syncthreads();
    int gid = bid * 1024 + threadIdx.x;
    if (gid < NN) {
        int o = g_off[gid] + sbase;
        g_off[gid] = o;
        g_cnt[gid] = o;   // becomes the bucket cursor
    }
    if (bid == 0 && threadIdx.x == 0) g_off[NN] = E;
}

// ---------------------------------------------------------------------------
// K3: bucket edges into CSR slots. 4 edges/thread (int4 loads) for MLP.
// ---------------------------------------------------------------------------
__global__ void bucket_kernel(const int* __restrict__ src,
                              const int* __restrict__ dst, int E) {
    int i = (blockIdx.x * blockDim.x + threadIdx.x) * 4;
    if (i + 3 < E) {
        int4 s = *reinterpret_cast<const int4*>(src + i);
        int4 d = *reinterpret_cast<const int4*>(dst + i);
        int p0 = atomicAdd(&g_cnt[d.x], 1);
        int p1 = atomicAdd(&g_cnt[d.y], 1);
        int p2 = atomicAdd(&g_cnt[d.z], 1);
        int p3 = atomicAdd(&g_cnt[d.w], 1);
        g_eidx[p0] = s.x;
        g_eidx[p1] = s.y;
        g_eidx[p2] = s.z;
        g_eidx[p3] = s.w;
    } else {
        for (int u = 0; u < 4 && i + u < E; u++) {
            int pos = atomicAdd(&g_cnt[dst[i + u]], 1);
            g_eidx[pos] = src[i + u];
        }
    }
}

// ---------------------------------------------------------------------------
// K4: fused gather-mean + GEMM + ReLU. Persistent blocks of 8 warps.
// Phase A: warp w gathers node g0+w's mean into xs[w][64] (coalesced 256B
//          float2 gathers, MLP=4, parallel index fetch).
// Phase B: thread (j = tid&63, slot = tid>>6) computes out[node][j] for
//          2 nodes, with W row j held in 64 REGISTERS (loaded once per block
//          lifetime — zero per-node W smem traffic) and x read as float4
//          broadcast LDS (1 LDS per 4 FMA).
// ---------------------------------------------------------------------------
__global__ void __launch_bounds__(256)
fused_kernel(const float* __restrict__ h,
             const float* __restrict__ W, const float* __restrict__ b,
             float* __restrict__ out, int N) {
    __shared__ __align__(16) float xs[8][DF];
    __shared__ int sdeg[8];

    const int tid = threadIdx.x;
    const int lane = tid & 31;
    const int warp = tid >> 5;
    const int j = tid & 63;
    const int slot = tid >> 6;          // 0..3
    const unsigned FULL = 0xffffffffu;

    float Wr[DF];
#pragma unroll
    for (int k = 0; k < DF; k++) Wr[k] = W[j * DF + k];
    const float bj = b[j];

    for (int g0 = blockIdx.x * 8; g0 < N; g0 += gridDim.x * 8) {
        // ---- Phase A: gather means ----
        const int node = g0 + warp;
        if (node < N) {
            const int beg = g_off[node];
            const int end = g_off[node + 1];
            const int deg = end - beg;

            float s0 = 0.f, s1 = 0.f;
            for (int base = beg; base < end; base += 32) {
                int idx = base + lane;
                int si = (idx < end) ? g_eidx[idx] : 0;
                int n = min(32, end - base);
                int t = 0;
                for (; t + 3 < n; t += 4) {
                    int ia = __shfl_sync(FULL, si, t);
                    int ib = __shfl_sync(FULL, si, t + 1);
                    int ic = __shfl_sync(FULL, si, t + 2);
                    int id = __shfl_sync(FULL, si, t + 3);
                    float2 va = *reinterpret_cast<const float2*>(h + (size_t)ia * DF + lane * 2);
                    float2 vb = *reinterpret_cast<const float2*>(h + (size_t)ib * DF + lane * 2);
                    float2 vc = *reinterpret_cast<const float2*>(h + (size_t)ic * DF + lane * 2);
                    float2 vd = *reinterpret_cast<const float2*>(h + (size_t)id * DF + lane * 2);
                    s0 += (va.x + vb.x) + (vc.x + vd.x);
                    s1 += (va.y + vb.y) + (vc.y + vd.y);
                }
                for (; t < n; t++) {
                    int ia = __shfl_sync(FULL, si, t);
                    float2 va = *reinterpret_cast<const float2*>(h + (size_t)ia * DF + lane * 2);
                    s0 += va.x;
                    s1 += va.y;
                }
            }
            const float inv = (deg > 0) ? (1.0f / (float)deg) : 0.0f;
            xs[warp][2 * lane]     = s0 * inv;
            xs[warp][2 * lane + 1] = s1 * inv;
            if (lane == 0) sdeg[warp] = deg;
        }
        __syncthreads();

        // ---- Phase B: out = relu(W @ x + b), 2 nodes per thread ----
#pragma unroll
        for (int sub = 0; sub < 2; sub++) {
            const int w = slot + sub * 4;
            const int n2 = g0 + w;
            if (n2 < N) {
                float acc = bj;
#pragma unroll
                for (int k = 0; k < DF; k += 4) {
                    float4 xk = *reinterpret_cast<const float4*>(&xs[w][k]);
                    acc = fmaf(Wr[k],     xk.x, acc);
                    acc = fmaf(Wr[k + 1], xk.y, acc);
                    acc = fmaf(Wr[k + 2], xk.z, acc);
                    acc = fmaf(Wr[k + 3], xk.w, acc);
                }
                out[(size_t)n2 * DF + j] = (sdeg[w] > 0) ? fmaxf(acc, 0.0f) : 0.0f;
            }
        }
        __syncthreads();
    }
}

// ---------------------------------------------------------------------------
extern "C" void kernel_launch(void* const* d_in, const int* in_sizes, int n_in,
                              void* d_out, int out_size) {
    const float* h   = (const float*)d_in[0];
    const int*   src = (const int*)d_in[1];
    const int*   dst = (const int*)d_in[2];
    const float* W   = (const float*)d_in[3];
    const float* b   = (const float*)d_in[4];
    float* out = (float*)d_out;

    const int N = in_sizes[0] / DF;   // 100000
    int E = in_sizes[1];              // 1600000
    if (E > NE) E = NE;

    zero_kernel<<<(NN + 255) / 256, 256>>>();
    count_kernel<<<(E / 4 + 255) / 256, 256>>>(dst, E);
    scanA_kernel<<<NB, 1024>>>();
    scanC_kernel<<<NB, 1024>>>(E);
    bucket_kernel<<<(E / 4 + 255) / 256, 256>>>(src, dst, E);
    fused_kernel<<<296, 256>>>(h, W, b, out, N);
}

// round 6
// speedup vs baseline: 1.5023x; 1.5023x over previous
#include <cuda_runtime.h>
#include <cstdint>

#define NN 100000
#define NE 1600000
#define DF 64
#define NB 98   // ceil(NN / 1024)

// Scratch (allocation-free rule: __device__ globals)
__device__ int g_cnt[NN];        // degree counts, then bucket cursors
__device__ int g_off[NN + 1];    // CSR offsets
__device__ int g_bsum[128];      // per-block sums for the scan
__device__ int g_eidx[NE];       // CSR: src index per slot, grouped by dst

// ---------------------------------------------------------------------------
// K0: zero degree counters (graph replays require re-zeroing)
// ---------------------------------------------------------------------------
__global__ void zero_kernel() {
    int tid = blockIdx.x * blockDim.x + threadIdx.x;
    if (tid < NN) g_cnt[tid] = 0;
}

// ---------------------------------------------------------------------------
// K1: count in-degree per dst. 4 edges/thread (int4 load) for MLP.
// ---------------------------------------------------------------------------
__global__ void count_kernel(const int* __restrict__ dst, int E) {
    int i = (blockIdx.x * blockDim.x + threadIdx.x) * 4;
    if (i + 3 < E) {
        int4 d = *reinterpret_cast<const int4*>(dst + i);
        atomicAdd(&g_cnt[d.x], 1);
        atomicAdd(&g_cnt[d.y], 1);
        atomicAdd(&g_cnt[d.z], 1);
        atomicAdd(&g_cnt[d.w], 1);
    } else {
        for (int u = 0; u < 4 && i + u < E; u++)
            atomicAdd(&g_cnt[dst[i + u]], 1);
    }
}

// ---------------------------------------------------------------------------
// K2a: per-block (1024 elems) local exclusive scan of g_cnt -> g_off,
//      block totals -> g_bsum.
// ---------------------------------------------------------------------------
__global__ void __launch_bounds__(1024)
scanA_kernel() {
    __shared__ int wsum[32];
    const int tid = threadIdx.x;
    const int lane = tid & 31;
    const int wid = tid >> 5;
    int gid = blockIdx.x * 1024 + tid;

    int v = (gid < NN) ? g_cnt[gid] : 0;
    int x = v;
#pragma unroll
    for (int o = 1; o < 32; o <<= 1) {
        int t = __shfl_up_sync(0xffffffffu, x, o);
        if (lane >= o) x += t;
    }
    if (lane == 31) wsum[wid] = x;
    __syncthreads();
    if (tid < 32) {
        int y = wsum[tid];
#pragma unroll
        for (int o = 1; o < 32; o <<= 1) {
            int t = __shfl_up_sync(0xffffffffu, y, o);
            if (tid >= o) y += t;
        }
        wsum[tid] = y;
    }
    __syncthreads();
    int base = (wid > 0) ? wsum[wid - 1] : 0;
    int incl = x + base;
    if (gid < NN) g_off[gid] = incl - v;           // local exclusive
    if (tid == 1023) g_bsum[blockIdx.x] = incl;    // block total
}

// ---------------------------------------------------------------------------
// K2b: add block base (warp-reduce prior block sums inline); init cursors.
// ---------------------------------------------------------------------------
__global__ void __launch_bounds__(1024)
scanC_kernel(int E) {
    __shared__ int sbase;
    const int bid = blockIdx.x;
    if (threadIdx.x < 32) {
        int base = 0;
        for (int i = threadIdx.x; i < bid; i += 32) base += g_bsum[i];
#pragma unroll
        for (int o = 16; o > 0; o >>= 1)
            base += __shfl_down_sync(0xffffffffu, base, o);
        if (threadIdx.x == 0) sbase = base;
    }
    __syncthreads();
    int gid = bid * 1024 + threadIdx.x;
    if (gid < NN) {
        int o = g_off[gid] + sbase;
        g_off[gid] = o;
        g_cnt[gid] = o;   // becomes the bucket cursor
    }
    if (bid == 0 && threadIdx.x == 0) g_off[NN] = E;
}

// ---------------------------------------------------------------------------
// K3: bucket edges into CSR slots. 4 edges/thread (int4 loads) for MLP.
// ---------------------------------------------------------------------------
__global__ void bucket_kernel(const int* __restrict__ src,
                              const int* __restrict__ dst, int E) {
    int i = (blockIdx.x * blockDim.x + threadIdx.x) * 4;
    if (i + 3 < E) {
        int4 s = *reinterpret_cast<const int4*>(src + i);
        int4 d = *reinterpret_cast<const int4*>(dst + i);
        int p0 = atomicAdd(&g_cnt[d.x], 1);
        int p1 = atomicAdd(&g_cnt[d.y], 1);
        int p2 = atomicAdd(&g_cnt[d.z], 1);
        int p3 = atomicAdd(&g_cnt[d.w], 1);
        g_eidx[p0] = s.x;
        g_eidx[p1] = s.y;
        g_eidx[p2] = s.z;
        g_eidx[p3] = s.w;
    } else {
        for (int u = 0; u < 4 && i + u < E; u++) {
            int pos = atomicAdd(&g_cnt[dst[i + u]], 1);
            g_eidx[pos] = src[i + u];
        }
    }
}

// ---------------------------------------------------------------------------
// K4: fused gather-mean + GEMM + ReLU. NO inter-warp barriers (R4 structure).
// Each warp owns 4 consecutive nodes: gathers their means (coalesced 256B
// float2 gathers, parallel index fetch, MLP=4), then runs ONE epilogue pass
// where every smem W load is reused for all 4 nodes (4x less smem W traffic
// than R4), with W stored as float2 pairs (conflict-free LDS.64).
// ---------------------------------------------------------------------------
__global__ void __launch_bounds__(256)
fused_kernel(const float* __restrict__ h,
             const float* __restrict__ W, const float* __restrict__ b,
             float* __restrict__ out, int N) {
    // Wp[k*64 + j] = { W[j*64 + 2k], W[j*64 + 2k+1] },  k=0..31, j=0..63
    __shared__ __align__(16) float2 Wp[32 * DF];
    __shared__ float bs[DF];

    const int tid = threadIdx.x;
    for (int idx = tid; idx < DF * DF / 2; idx += 256) {
        int j = idx >> 5;          // 0..63
        int k = idx & 31;          // 0..31
        Wp[k * DF + j] = make_float2(W[j * DF + 2 * k], W[j * DF + 2 * k + 1]);
    }
    if (tid < DF) bs[tid] = b[tid];
    __syncthreads();

    const int lane = tid & 31;
    const int warp = tid >> 5;
    const unsigned FULL = 0xffffffffu;

    const int n0 = (blockIdx.x * 8 + warp) * 4;   // 4 nodes per warp
    if (n0 >= N) return;

    float x0[4], x1[4];          // lane's feature cols {2*lane, 2*lane+1} per node
    int degs[4];

#pragma unroll
    for (int m = 0; m < 4; m++) {
        const int node = n0 + m;
        float s0 = 0.f, s1 = 0.f;
        int deg = 0;
        if (node < N) {
            const int beg = g_off[node];
            const int end = g_off[node + 1];
            deg = end - beg;
            for (int base = beg; base < end; base += 32) {
                int idx = base + lane;
                int si = (idx < end) ? g_eidx[idx] : 0;   // 1 coalesced load / 32 edges
                int nn = min(32, end - base);
                int t = 0;
                for (; t + 3 < nn; t += 4) {              // MLP = 4 independent gathers
                    int ia = __shfl_sync(FULL, si, t);
                    int ib = __shfl_sync(FULL, si, t + 1);
                    int ic = __shfl_sync(FULL, si, t + 2);
                    int id = __shfl_sync(FULL, si, t + 3);
                    float2 va = *reinterpret_cast<const float2*>(h + (size_t)ia * DF + lane * 2);
                    float2 vb = *reinterpret_cast<const float2*>(h + (size_t)ib * DF + lane * 2);
                    float2 vc = *reinterpret_cast<const float2*>(h + (size_t)ic * DF + lane * 2);
                    float2 vd = *reinterpret_cast<const float2*>(h + (size_t)id * DF + lane * 2);
                    s0 += (va.x + vb.x) + (vc.x + vd.x);
                    s1 += (va.y + vb.y) + (vc.y + vd.y);
                }
                for (; t < nn; t++) {
                    int ia = __shfl_sync(FULL, si, t);
                    float2 va = *reinterpret_cast<const float2*>(h + (size_t)ia * DF + lane * 2);
                    s0 += va.x;
                    s1 += va.y;
                }
            }
        }
        const float inv = (deg > 0) ? (1.0f / (float)deg) : 0.0f;
        x0[m] = s0 * inv;
        x1[m] = s1 * inv;
        degs[m] = deg;
    }

    // ---- Epilogue: 4 nodes share every W smem load ----
    float accA[4], accB[4];      // out col j=lane, j=lane+32 per node
#pragma unroll
    for (int m = 0; m < 4; m++) { accA[m] = bs[lane]; accB[m] = bs[lane + 32]; }

#pragma unroll
    for (int k = 0; k < 32; k++) {
        float2 wA = Wp[k * DF + lane];        // {W[lane][2k],    W[lane][2k+1]}
        float2 wB = Wp[k * DF + lane + 32];   // {W[lane+32][2k], W[lane+32][2k+1]}
#pragma unroll
        for (int m = 0; m < 4; m++) {
            float xa = __shfl_sync(FULL, x0[m], k);   // x[2k]
            float xb = __shfl_sync(FULL, x1[m], k);   // x[2k+1]
            accA[m] = fmaf(wA.x, xa, accA[m]);
            accA[m] = fmaf(wA.y, xb, accA[m]);
            accB[m] = fmaf(wB.x, xa, accB[m]);
            accB[m] = fmaf(wB.y, xb, accB[m]);
        }
    }

#pragma unroll
    for (int m = 0; m < 4; m++) {
        const int node = n0 + m;
        if (node < N) {
            float* o = out + (size_t)node * DF;
            const bool nz = degs[m] > 0;
            o[lane]      = nz ? fmaxf(accA[m], 0.0f) : 0.0f;
            o[lane + 32] = nz ? fmaxf(accB[m], 0.0f) : 0.0f;
        }
    }
}

// ---------------------------------------------------------------------------
extern "C" void kernel_launch(void* const* d_in, const int* in_sizes, int n_in,
                              void* d_out, int out_size) {
    const float* h   = (const float*)d_in[0];
    const int*   src = (const int*)d_in[1];
    const int*   dst = (const int*)d_in[2];
    const float* W   = (const float*)d_in[3];
    const float* b   = (const float*)d_in[4];
    float* out = (float*)d_out;

    const int N = in_sizes[0] / DF;   // 100000
    int E = in_sizes[1];              // 1600000
    if (E > NE) E = NE;

    zero_kernel<<<(NN + 255) / 256, 256>>>();
    count_kernel<<<(E / 4 + 255) / 256, 256>>>(dst, E);
    scanA_kernel<<<NB, 1024>>>();
    scanC_kernel<<<NB, 1024>>>(E);
    bucket_kernel<<<(E / 4 + 255) / 256, 256>>>(src, dst, E);

    const int nodes_per_block = 8 * 4;
    fused_kernel<<<(N + nodes_per_block - 1) / nodes_per_block, 256>>>(h, W, b, out, N);
}